// round 3
// baseline (speedup 1.0000x reference)
#include <cuda_runtime.h>
#include <cstdint>

// ---------------------------------------------------------------------------
// TractBundle: 3 masked linears (A: 4096->1024 @64 conn, B: 4096->512 @64,
// C: 2048->512 @32), concat on last dim. B=8, S=1024 -> 8192 tokens.
// Sparse gather-FMA. R3 changes vs R2: 16 rows/warp (occ 3 blocks/SM),
// fma-tree accumulation (shorter dep chain), prefetched idx/w stream.
// ---------------------------------------------------------------------------

#define NROWS      2048       // 1024 A + 512 B + 512 C
#define ROWCAP     96         // max 64 entries + 8 slices * 3 pad = 88 -> 96
#define SLICE      512
#define XSTR       513        // 513 % 32 == 1 -> bank(lane*513 + idx) = lane+idx
#define NTOK       32
#define TPB        512        // 16 warps
#define RPW        16         // rows per warp
#define SMEM_FLOATS (NTOK * XSTR)   // 16416 floats = 65.7 KB

__device__ __align__(16) int   g_idx[NROWS * ROWCAP];   // byte offset within slice
__device__ __align__(16) float g_w  [NROWS * ROWCAP];
__device__ unsigned g_seg[NROWS * 8];                   // start | (padded_count<<16)

// ---------------------------------------------------------------------------
// Prep: one warp per dst row. Ballot-compact nonzero mask positions (ascending,
// so per-slice segments are contiguous), weight = w*m, pad each slice segment
// to a multiple of 4 entries with (0, 0.0f). Start offsets stay 4-aligned.
// ---------------------------------------------------------------------------
__global__ void prep_kernel(const float* __restrict__ wa, const float* __restrict__ ma,
                            const float* __restrict__ wb, const float* __restrict__ mb,
                            const float* __restrict__ wc, const float* __restrict__ mc)
{
    int gw   = (blockIdx.x * blockDim.x + threadIdx.x) >> 5;
    int lane = threadIdx.x & 31;
    if (gw >= NROWS) return;

    const float *w, *m; int nsl;
    if (gw < 1024)      { w = wa + (size_t)gw * 4096;        m = ma + (size_t)gw * 4096;        nsl = 8; }
    else if (gw < 1536) { w = wb + (size_t)(gw-1024) * 4096; m = mb + (size_t)(gw-1024) * 4096; nsl = 8; }
    else                { w = wc + (size_t)(gw-1536) * 2048; m = mc + (size_t)(gw-1536) * 2048; nsl = 4; }

    int base = gw * ROWCAP;
    int cnt  = 0;
    unsigned ltmask = (1u << lane) - 1u;

    for (int k = 0; k < nsl; k++) {
        int start = cnt;
        for (int c = 0; c < SLICE; c += 32) {
            int   s  = k * SLICE + c + lane;
            float mv = m[s];
            bool  p  = (mv != 0.0f);
            unsigned b = __ballot_sync(0xffffffffu, p);
            if (p) {
                int pos = cnt + __popc(b & ltmask);
                g_idx[base + pos] = (c + lane) * 4;   // byte offset within slice
                g_w  [base + pos] = w[s] * mv;
            }
            cnt += __popc(b);
        }
        int n    = cnt - start;
        int npad = (n + 3) & ~3;
        if (lane < npad - n) {                        // pad with harmless entries
            g_idx[base + cnt + lane] = 0;
            g_w  [base + cnt + lane] = 0.0f;
        }
        cnt = start + npad;
        if (lane == 0) g_seg[gw * 8 + k] = (unsigned)start | ((unsigned)npad << 16);
    }
}

// ---------------------------------------------------------------------------
// Gather kernel. Grid: (256 token tiles, 8 row groups of 256 rows).
//   grp 0-3: rows    0-1023 (x_a)   grp 4-5: rows 1024-1535 (x_b)
//   grp 6-7: rows 1536-2047 (x_c)
// Block: 512 threads / 16 warps; warp w owns 16 rows -> 16 register accs.
// Lane l <-> token t0+l. Per K-slice: cp.async stage -> gather/FMA.
// ---------------------------------------------------------------------------
__device__ __forceinline__ uint32_t smem_u32(const void* p) {
    uint32_t a;
    asm("{ .reg .u64 t; cvta.to.shared.u64 t, %1; cvt.u32.u64 %0, t; }" : "=r"(a) : "l"(p));
    return a;
}

__global__ void __launch_bounds__(TPB, 3)
gather_kernel(const float* __restrict__ xa, const float* __restrict__ xb,
              const float* __restrict__ xc, float* __restrict__ out)
{
    __shared__ float sm[SMEM_FLOATS];

    const int grp = blockIdx.y;
    const int t0  = blockIdx.x * NTOK;

    const float* x; int S, nsl, row0g;
    if (grp < 4)       { x = xa; S = 4096; nsl = 8; row0g = grp * 256; }
    else if (grp < 6)  { x = xb; S = 4096; nsl = 8; row0g = 1024 + (grp - 4) * 256; }
    else               { x = xc; S = 2048; nsl = 4; row0g = 1536 + (grp - 6) * 256; }

    const int tid    = threadIdx.x;
    const int lane   = tid & 31;
    const int warp   = tid >> 5;
    const int myrow0 = row0g + warp * RPW;   // global row == output column

    float acc[RPW];
#pragma unroll
    for (int r = 0; r < RPW; r++) acc[r] = 0.0f;

    const uint32_t sm_base = smem_u32(sm);
    const uint32_t xlane   = sm_base + (uint32_t)(lane * XSTR) * 4u;

    for (int k = 0; k < nsl; k++) {
        if (k) __syncthreads();

        // --- stage slice: 32 tokens x 512 floats, 4B cp.async, conflict-free ---
        const float* xsrc = x + (size_t)t0 * S + k * SLICE;
#pragma unroll
        for (int it = 0; it < (NTOK * SLICE) / TPB; it++) {
            int p  = tid + it * TPB;
            int ti = p >> 9;
            int c  = p & (SLICE - 1);
            uint32_t dst = sm_base + (uint32_t)(ti * XSTR + c) * 4u;
            const float* src = xsrc + (size_t)ti * S + c;
            asm volatile("cp.async.ca.shared.global [%0], [%1], 4;\n"
                         :: "r"(dst), "l"(src) : "memory");
        }
        asm volatile("cp.async.commit_group;\n" ::: "memory");
        asm volatile("cp.async.wait_group 0;\n" ::: "memory");
        __syncthreads();

        // --- gather + FMA over this slice's segment of each of my 16 rows ---
#pragma unroll
        for (int r = 0; r < RPW; r++) {
            int row = myrow0 + r;
            unsigned seg = __ldg(&g_seg[row * 8 + k]);
            int ebase = row * ROWCAP + (int)(seg & 0xffffu);
            int nq    = (int)(seg >> 18);   // quads (count is multiple of 4)
            const int4*   ip = (const int4*)  (g_idx + ebase);
            const float4* wp = (const float4*)(g_w   + ebase);
            float a = acc[r];
            if (nq > 0) {
                int4   ib = __ldg(ip);
                float4 wv = __ldg(wp);
                for (int q = 1; q < nq; q++) {
                    int4   ibn = __ldg(ip + q);    // prefetch next quad
                    float4 wvn = __ldg(wp + q);
                    float x0, x1, x2, x3;
                    asm volatile("ld.shared.f32 %0, [%1];" : "=f"(x0) : "r"(xlane + (uint32_t)ib.x));
                    asm volatile("ld.shared.f32 %0, [%1];" : "=f"(x1) : "r"(xlane + (uint32_t)ib.y));
                    asm volatile("ld.shared.f32 %0, [%1];" : "=f"(x2) : "r"(xlane + (uint32_t)ib.z));
                    asm volatile("ld.shared.f32 %0, [%1];" : "=f"(x3) : "r"(xlane + (uint32_t)ib.w));
                    float p0 = fmaf(x1, wv.y, x0 * wv.x);   // tree: 2 indep chains
                    float p1 = fmaf(x3, wv.w, x2 * wv.z);
                    a = (a + p0) + p1;
                    ib = ibn; wv = wvn;
                }
                {   // tail quad
                    float x0, x1, x2, x3;
                    asm volatile("ld.shared.f32 %0, [%1];" : "=f"(x0) : "r"(xlane + (uint32_t)ib.x));
                    asm volatile("ld.shared.f32 %0, [%1];" : "=f"(x1) : "r"(xlane + (uint32_t)ib.y));
                    asm volatile("ld.shared.f32 %0, [%1];" : "=f"(x2) : "r"(xlane + (uint32_t)ib.z));
                    asm volatile("ld.shared.f32 %0, [%1];" : "=f"(x3) : "r"(xlane + (uint32_t)ib.w));
                    float p0 = fmaf(x1, wv.y, x0 * wv.x);
                    float p1 = fmaf(x3, wv.w, x2 * wv.z);
                    a = (a + p0) + p1;
                }
            }
            acc[r] = a;
        }
    }

    // --- epilogue: smem transpose -> coalesced STG (16 rows per warp) ---
    __syncthreads();
    float* tw = sm + warp * (NTOK * (RPW + 1));     // 32*17 floats per warp
#pragma unroll
    for (int r = 0; r < RPW; r++) tw[lane * (RPW + 1) + r] = acc[r];  // stride 17: conflict-free
    __syncwarp();
#pragma unroll
    for (int tt = 0; tt < NTOK; tt++) {
        if (lane < RPW) {
            float v = tw[tt * (RPW + 1) + lane];
            out[(size_t)(t0 + tt) * 2048 + myrow0 + lane] = v;
        }
    }
}

// ---------------------------------------------------------------------------
extern "C" void kernel_launch(void* const* d_in, const int* in_sizes, int n_in,
                              void* d_out, int out_size)
{
    const float *x_a, *w_a, *m_a, *x_b, *w_b, *m_b, *x_c, *w_c, *m_c;
    if (n_in >= 9 && in_sizes[1] == 4194304) {
        // dict insertion order: x_a, w_a, m_a, x_b, w_b, m_b, x_c, w_c, m_c
        x_a = (const float*)d_in[0]; w_a = (const float*)d_in[1]; m_a = (const float*)d_in[2];
        x_b = (const float*)d_in[3]; w_b = (const float*)d_in[4]; m_b = (const float*)d_in[5];
        x_c = (const float*)d_in[6]; w_c = (const float*)d_in[7]; m_c = (const float*)d_in[8];
    } else {
        // reference signature order: x_a, x_b, x_c, w_a, w_b, w_c, m_a, m_b, m_c
        x_a = (const float*)d_in[0]; x_b = (const float*)d_in[1]; x_c = (const float*)d_in[2];
        w_a = (const float*)d_in[3]; w_b = (const float*)d_in[4]; w_c = (const float*)d_in[5];
        m_a = (const float*)d_in[6]; m_b = (const float*)d_in[7]; m_c = (const float*)d_in[8];
    }

    float* out = (float*)d_out;

    prep_kernel<<<NROWS / 8, 256>>>(w_a, m_a, w_b, m_b, w_c, m_c);

    dim3 grid(8192 / NTOK, 8);
    gather_kernel<<<grid, TPB>>>(x_a, x_b, x_c, out);
}

// round 4
// speedup vs baseline: 1.2431x; 1.2431x over previous
#include <cuda_runtime.h>
#include <cstdint>

// ---------------------------------------------------------------------------
// TractBundle: 3 masked linears (A: 4096->1024 @64 conn, B: 4096->512 @64,
// C: 2048->512 @32), concat on last dim. B=8, S=1024 -> 8192 tokens.
// Sparse gather-FMA. R4: idx/w streams consumed via half-warp coalesced
// preload -> smem scratch -> uniform (broadcast) LDS, two-row interleaved
// inner loop, 32 rows/warp.
// ---------------------------------------------------------------------------

#define NROWS      2048       // 1024 A + 512 B + 512 C
#define ROWCAP     96         // entries per row (max 64 + per-slice padding)
#define RQ         (ROWCAP/4) // 24 quads per row
#define SLICE      512
#define XSTR       513        // odd stride -> conflict-free gathers
#define NTOK       32
#define TPB        512        // 16 warps
#define RPW        32         // rows per warp
// dynamic smem: x tile 16896 floats (also epilogue), + scratch 16 warps * 32 * (int4+float4)
#define SM_X_FLOATS   16896
#define SM_SIDX_OFF   (SM_X_FLOATS * 4)                 // bytes
#define SM_SW_OFF     (SM_SIDX_OFF + 16 * 32 * 16)
#define SMEM_BYTES    (SM_SW_OFF + 16 * 32 * 16)        // 67584 + 8192 + 8192 = 83968

__device__ __align__(16) int   g_idx[NROWS * ROWCAP];   // byte offsets within slice
__device__ __align__(16) float g_w  [NROWS * ROWCAP];
__device__ __align__(8)  unsigned g_seg[8 * NROWS];     // [slice][row]: qstart | (nq<<16)

// ---------------------------------------------------------------------------
// Prep: one warp per dst row. Ballot-compact nonzero mask positions (ascending
// -> per-slice segments contiguous), weight = w*m, pad each slice segment to a
// multiple of 4 entries with (0, 0.0f).
// ---------------------------------------------------------------------------
__global__ void prep_kernel(const float* __restrict__ wa, const float* __restrict__ ma,
                            const float* __restrict__ wb, const float* __restrict__ mb,
                            const float* __restrict__ wc, const float* __restrict__ mc)
{
    int gw   = (blockIdx.x * blockDim.x + threadIdx.x) >> 5;
    int lane = threadIdx.x & 31;
    if (gw >= NROWS) return;

    const float *w, *m; int nsl;
    if (gw < 1024)      { w = wa + (size_t)gw * 4096;        m = ma + (size_t)gw * 4096;        nsl = 8; }
    else if (gw < 1536) { w = wb + (size_t)(gw-1024) * 4096; m = mb + (size_t)(gw-1024) * 4096; nsl = 8; }
    else                { w = wc + (size_t)(gw-1536) * 2048; m = mc + (size_t)(gw-1536) * 2048; nsl = 4; }

    int base = gw * ROWCAP;
    int cnt  = 0;
    unsigned ltmask = (1u << lane) - 1u;

    for (int k = 0; k < 8; k++) {
        if (k >= nsl) {                      // empty segments for C's upper slices
            if (lane == 0) g_seg[k * NROWS + gw] = (unsigned)(cnt >> 2);
            continue;
        }
        int start = cnt;
        for (int c = 0; c < SLICE; c += 32) {
            int   s  = k * SLICE + c + lane;
            float mv = m[s];
            bool  p  = (mv != 0.0f);
            unsigned b = __ballot_sync(0xffffffffu, p);
            if (p) {
                int pos = cnt + __popc(b & ltmask);
                g_idx[base + pos] = (c + lane) * 4;   // byte offset within slice
                g_w  [base + pos] = w[s] * mv;
            }
            cnt += __popc(b);
        }
        int n    = cnt - start;
        int npad = (n + 3) & ~3;
        if (lane < npad - n) {
            g_idx[base + cnt + lane] = 0;
            g_w  [base + cnt + lane] = 0.0f;
        }
        cnt = start + npad;
        if (lane == 0)
            g_seg[k * NROWS + gw] = (unsigned)(start >> 2) | ((unsigned)(npad >> 2) << 16);
    }
}

// ---------------------------------------------------------------------------
// Gather kernel. Grid: (256 token tiles, 4 row groups of 512 rows).
// Block: 512 threads / 16 warps; warp owns 32 rows (16 pairs).
// Lane l <-> token t0+l. Per K-slice: cp.async stage x; per row-pair:
// half-warp coalesced preload of the pair's quads -> scratch -> uniform LDS.
// ---------------------------------------------------------------------------
__device__ __forceinline__ uint32_t smem_u32(const void* p) {
    uint32_t a;
    asm("{ .reg .u64 t; cvta.to.shared.u64 t, %1; cvt.u32.u64 %0, t; }" : "=r"(a) : "l"(p));
    return a;
}

__global__ void __launch_bounds__(TPB, 2)
gather_kernel(const float* __restrict__ xa, const float* __restrict__ xb,
              const float* __restrict__ xc, float* __restrict__ out)
{
    extern __shared__ float sm[];

    const int grp = blockIdx.y;
    const int t0  = blockIdx.x * NTOK;

    const float* x; int S, nsl, row0g;
    if (grp <= 1)      { x = xa; S = 4096; nsl = 8; row0g = grp * 512; }
    else if (grp == 2) { x = xb; S = 4096; nsl = 8; row0g = 1024; }
    else               { x = xc; S = 2048; nsl = 4; row0g = 1536; }

    const int tid    = threadIdx.x;
    const int lane   = tid & 31;
    const int warp   = tid >> 5;
    const int half   = lane >> 4;      // 0: even row of pair, 1: odd row
    const int lh     = lane & 15;
    const int myrow0 = row0g + warp * RPW;

    float acc[RPW];
#pragma unroll
    for (int r = 0; r < RPW; r++) acc[r] = 0.0f;

    const uint32_t sm_base = smem_u32(sm);
    const uint32_t xlane   = sm_base + (uint32_t)(lane * XSTR) * 4u;
    int4*   sidx = (int4*)  ((char*)sm + SM_SIDX_OFF) + warp * 32;
    float4* swq  = (float4*)((char*)sm + SM_SW_OFF)   + warp * 32;

    for (int k = 0; k < nsl; k++) {
        if (k) __syncthreads();

        // --- stage slice: 32 tokens x 512 floats, strength-reduced addresses ---
        {
            const float* src = x + (size_t)t0 * S + k * SLICE + tid;  // ti = it, c = tid
            uint32_t dst = sm_base + (uint32_t)tid * 4u;
#pragma unroll
            for (int it = 0; it < NTOK; it++) {
                asm volatile("cp.async.ca.shared.global [%0], [%1], 4;\n"
                             :: "r"(dst), "l"(src) : "memory");
                dst += XSTR * 4;
                src += S;
            }
        }
        asm volatile("cp.async.commit_group;\n" ::: "memory");
        asm volatile("cp.async.wait_group 0;\n" ::: "memory");
        __syncthreads();

        const unsigned* segk = g_seg + k * NROWS + myrow0;

#pragma unroll 1
        for (int rp = 0; rp < RPW; rp += 2) {
            int row0 = myrow0 + rp;
            uint2 segp = *(const uint2*)(segk + rp);
            int nq0 = (int)(segp.x >> 16);
            int nq1 = (int)(segp.y >> 16);

            // --- half-warp coalesced preload of this pair's quads -> scratch ---
            unsigned sh  = half ? segp.y : segp.x;
            int nqh  = (int)(sh >> 16);
            int qoff = (nqh > 0) ? (lh < nqh ? lh : nqh - 1) : 0;
            int qidx = (row0 + half) * RQ + (int)(sh & 0xffffu) + qoff;
            sidx[lane] = __ldg((const int4*)g_idx + qidx);
            swq [lane] = __ldg((const float4*)g_w + qidx);
            __syncwarp();

            float a0 = acc[rp], a1 = acc[rp + 1];
            int mq = nq0 > nq1 ? nq0 : nq1;
            for (int q = 0; q < mq; q++) {
                int4   i0 = sidx[q];        // uniform -> broadcast LDS
                float4 w0 = swq[q];
                int4   i1 = sidx[16 + q];
                float4 w1 = swq[16 + q];
                if (q < nq0) {
                    float x0, x1, x2, x3;
                    asm volatile("ld.shared.f32 %0, [%1];" : "=f"(x0) : "r"(xlane + (uint32_t)i0.x));
                    asm volatile("ld.shared.f32 %0, [%1];" : "=f"(x1) : "r"(xlane + (uint32_t)i0.y));
                    asm volatile("ld.shared.f32 %0, [%1];" : "=f"(x2) : "r"(xlane + (uint32_t)i0.z));
                    asm volatile("ld.shared.f32 %0, [%1];" : "=f"(x3) : "r"(xlane + (uint32_t)i0.w));
                    float p0 = fmaf(x1, w0.y, x0 * w0.x);
                    float p1 = fmaf(x3, w0.w, x2 * w0.z);
                    a0 = (a0 + p0) + p1;
                }
                if (q < nq1) {
                    float y0, y1, y2, y3;
                    asm volatile("ld.shared.f32 %0, [%1];" : "=f"(y0) : "r"(xlane + (uint32_t)i1.x));
                    asm volatile("ld.shared.f32 %0, [%1];" : "=f"(y1) : "r"(xlane + (uint32_t)i1.y));
                    asm volatile("ld.shared.f32 %0, [%1];" : "=f"(y2) : "r"(xlane + (uint32_t)i1.z));
                    asm volatile("ld.shared.f32 %0, [%1];" : "=f"(y3) : "r"(xlane + (uint32_t)i1.w));
                    float p0 = fmaf(y1, w1.y, y0 * w1.x);
                    float p1 = fmaf(y3, w1.w, y2 * w1.z);
                    a1 = (a1 + p0) + p1;
                }
            }
            acc[rp] = a0; acc[rp + 1] = a1;
            __syncwarp();   // scratch reads done before next pair's STS
        }
    }

    // --- epilogue: smem transpose -> coalesced STG ---
    __syncthreads();
    float* tw = sm + warp * (32 * 33);
#pragma unroll
    for (int r = 0; r < RPW; r++) tw[lane * 33 + r] = acc[r];   // bank = lane+r
    __syncwarp();
#pragma unroll
    for (int tt = 0; tt < 32; tt++) {
        float v = tw[tt * 33 + lane];                            // bank = tt+lane
        out[(size_t)(t0 + tt) * 2048 + myrow0 + lane] = v;
    }
}

// ---------------------------------------------------------------------------
extern "C" void kernel_launch(void* const* d_in, const int* in_sizes, int n_in,
                              void* d_out, int out_size)
{
    const float *x_a, *w_a, *m_a, *x_b, *w_b, *m_b, *x_c, *w_c, *m_c;
    if (n_in >= 9 && in_sizes[1] == 4194304) {
        x_a = (const float*)d_in[0]; w_a = (const float*)d_in[1]; m_a = (const float*)d_in[2];
        x_b = (const float*)d_in[3]; w_b = (const float*)d_in[4]; m_b = (const float*)d_in[5];
        x_c = (const float*)d_in[6]; w_c = (const float*)d_in[7]; m_c = (const float*)d_in[8];
    } else {
        x_a = (const float*)d_in[0]; x_b = (const float*)d_in[1]; x_c = (const float*)d_in[2];
        w_a = (const float*)d_in[3]; w_b = (const float*)d_in[4]; w_c = (const float*)d_in[5];
        m_a = (const float*)d_in[6]; m_b = (const float*)d_in[7]; m_c = (const float*)d_in[8];
    }

    float* out = (float*)d_out;

    static int attr_done = 0;
    if (!attr_done) {
        cudaFuncSetAttribute(gather_kernel, cudaFuncAttributeMaxDynamicSharedMemorySize, SMEM_BYTES);
        attr_done = 1;
    }

    prep_kernel<<<NROWS / 8, 256>>>(w_a, m_a, w_b, m_b, w_c, m_c);

    dim3 grid(8192 / NTOK, 4);
    gather_kernel<<<grid, TPB, SMEM_BYTES>>>(x_a, x_b, x_c, out);
}